// round 15
// baseline (speedup 1.0000x reference)
#include <cuda_runtime.h>
#include <cstdint>

#define T_ 256
#define D_ 64
#define H_ 256
#define B_ 512
#define ROWSC 8          // batch rows per cluster
#define JH 128           // output columns per CTA
#define NCTA 128
#define THREADS 512      // (kq:2) | (j0:7)

#define VS 260           // vector row stride (floats), 16B aligned
#define XS 68
#define NSLOT 48         // 0-7 r(A) | 8-15 z(A) | 16-23 n(A) | 24-31 i(x) | 32-39 r(x) | 40-47 z(x)

// dynamic smem layout (floats)
#define OFF_H    0
#define OFF_ODE  (OFF_H + ROWSC * VS)
#define OFF_A1   (OFF_ODE + ROWSC * VS)
#define OFF_X    (OFF_A1 + ROWSC * VS)
#define OFF_MK   (OFF_X + ROWSC * XS)
#define OFF_DT   (OFF_MK + 8)
#define OFF_PART (OFF_DT + T_)
#define SMEM_FLOATS (OFF_PART + 4 * NSLOT * JH)
#define SMEM_BYTES (SMEM_FLOATS * 4)

// packed: P[k4 * O + o] = float4{ W[o][4k4+0..3] }
__device__ float4 g_w1p[(H_ / 4) * H_];
__device__ float4 g_w2p[(H_ / 4) * H_];
__device__ float4 g_whhp[(H_ / 4) * (3 * H_)];
__device__ float4 g_wihp[(D_ / 4) * (3 * H_)];
__device__ float4 g_woutp[(H_ / 4) * H_];
__device__ float g_dt[T_];

#define N_W1 ((H_ / 4) * H_)
#define N_WHH ((H_ / 4) * (3 * H_))
#define N_WIH ((D_ / 4) * (3 * H_))
#define PK_TOTAL (3 * N_W1 + N_WHH + N_WIH)

__global__ void pack_all_kernel(const float* __restrict__ w1,
                                const float* __restrict__ w2,
                                const float* __restrict__ whh,
                                const float* __restrict__ wih,
                                const float* __restrict__ wout,
                                const float* __restrict__ tps) {
    int idx = blockIdx.x * blockDim.x + threadIdx.x;
    if (idx < T_) {
        g_dt[idx] = (idx == 0) ? (tps[0] - (tps[0] - 0.01f))
                               : (tps[idx] - tps[idx - 1]);
    }
    if (idx >= PK_TOTAL) return;
    const float* src; float4* dst; int O, K, local = idx;
    if (local < N_W1) { src = w1; dst = g_w1p; O = H_; K = H_; }
    else if ((local -= N_W1) < N_W1) { src = w2; dst = g_w2p; O = H_; K = H_; }
    else if ((local -= N_W1) < N_WHH) { src = whh; dst = g_whhp; O = 3 * H_; K = H_; }
    else if ((local -= N_WHH) < N_WIH) { src = wih; dst = g_wihp; O = 3 * H_; K = D_; }
    else { local -= N_WIH; src = wout; dst = g_woutp; O = H_; K = H_; }
    int k4 = local / O;
    int o = local % O;
    const float* s = src + (size_t)o * K + 4 * k4;
    dst[local] = make_float4(s[0], s[1], s[2], s[3]);
}

typedef unsigned long long ull;
__device__ __forceinline__ ull ffma2(ull a, ull b, ull c) {
    ull d; asm("fma.rn.f32x2 %0, %1, %2, %3;" : "=l"(d) : "l"(a), "l"(b), "l"(c)); return d;
}
__device__ __forceinline__ float hadd2(ull v) {
    float2 f; asm("mov.b64 {%0, %1}, %2;" : "=f"(f.x), "=f"(f.y) : "l"(v));
    return f.x + f.y;
}
__device__ __forceinline__ float sigmoidf_(float v) { return 1.0f / (1.0f + expf(-v)); }

__device__ __forceinline__ void sts_peer_f32(const void* laddr, uint32_t peer, float v) {
    uint32_t la = (uint32_t)__cvta_generic_to_shared(laddr), ra;
    asm("mapa.shared::cluster.u32 %0, %1, %2;" : "=r"(ra) : "r"(la), "r"(peer));
    asm volatile("st.shared::cluster.b32 [%0], %1;" :: "r"(ra), "r"(__float_as_uint(v)) : "memory");
}
__device__ __forceinline__ void cluster_sync_() {
    asm volatile("barrier.cluster.arrive.aligned;" ::: "memory");
    asm volatile("barrier.cluster.wait.aligned;" ::: "memory");
}
__device__ __forceinline__ void cluster_arrive_() {
    asm volatile("barrier.cluster.arrive.aligned;" ::: "memory");
}
__device__ __forceinline__ void cluster_wait_() {
    asm volatile("barrier.cluster.wait.aligned;" ::: "memory");
}

// 8-row GEMM over 16 quads, weight ring wb[8] PRELOADED by caller (slots 0..7).
__device__ __forceinline__ void gemm8p(ull acc[8], const ulonglong2* __restrict__ wp, int wstep,
                                       const float* __restrict__ vbase, ulonglong2 wb[8]) {
#pragma unroll
    for (int kk = 0; kk < 16; kk++) {
        ulonglong2 w = wb[kk & 7];
        if (kk + 8 < 16) wb[kk & 7] = wp[(kk + 8) * wstep];
#pragma unroll
        for (int r = 0; r < 8; r++) {
            ulonglong2 v = *reinterpret_cast<const ulonglong2*>(vbase + r * VS + 4 * kk);
            acc[r] = ffma2(w.x, v.x, acc[r]);
            acc[r] = ffma2(w.y, v.y, acc[r]);
        }
    }
}

#define PRELOAD8(WB, WP, WSTEP)                        \
    _Pragma("unroll")                                  \
    for (int i_ = 0; i_ < 8; i_++) (WB)[i_] = (WP)[i_ * (WSTEP)];

#define PART4(kq_, slot_, j_) sm[OFF_PART + ((kq_) * NSLOT + (slot_)) * JH + (j_)]

__global__ void __launch_bounds__(THREADS, 1) __cluster_dims__(2, 1, 1)
gruode_kernel(const float* __restrict__ x,
              const float* __restrict__ mask,
              const float* __restrict__ b_ih,
              const float* __restrict__ b_hh,
              const float* __restrict__ b1,
              const float* __restrict__ b2,
              const float* __restrict__ b_out,
              float* __restrict__ out) {
    extern __shared__ float sm[];
    float* hbuf = sm + OFF_H;
    float* odebuf = sm + OFF_ODE;
    float* a1buf = sm + OFF_A1;
    float* xbuf = sm + OFF_X;
    float* smk = sm + OFF_MK;
    float* sdt = sm + OFF_DT;

    const ulonglong2* w1u = reinterpret_cast<const ulonglong2*>(g_w1p);
    const ulonglong2* w2u = reinterpret_cast<const ulonglong2*>(g_w2p);
    const ulonglong2* whhu = reinterpret_cast<const ulonglong2*>(g_whhp);
    const ulonglong2* wihu = reinterpret_cast<const ulonglong2*>(g_wihp);
    const ulonglong2* woutu = reinterpret_cast<const ulonglong2*>(g_woutp);

    const int tid = threadIdx.x;
    const int j0 = tid & (JH - 1);
    const int kq = tid >> 7;           // 0..3 : k-quarter AND row-ownership (rows 2kq, 2kq+1)
    uint32_t rank;
    asm("mov.u32 %0, %%cluster_ctarank;" : "=r"(rank));
    const uint32_t peer = rank ^ 1u;
    const int jg = (int)rank * JH + j0;
    const int row0 = (blockIdx.x >> 1) * ROWSC;
    const int ro0 = 2 * kq, ro1 = 2 * kq + 1;

    for (int idx = tid; idx < ROWSC * VS; idx += THREADS) hbuf[idx] = 0.0f;
    for (int i = tid; i < T_; i += THREADS) sdt[i] = g_dt[i];

    float hc0 = 0.0f, hc1 = 0.0f, hl0 = 0.0f, hl1 = 0.0f;
    float se0 = 0.0f, se1 = 0.0f, ho0 = 0.0f, ho1 = 0.0f;

    const float b1j = b1[jg];
    const float b2j = b2[jg];
    const float brz_r = b_ih[jg] + b_hh[jg];
    const float brz_z = b_ih[H_ + jg] + b_hh[H_ + jg];
    const float bin_ = b_ih[2 * H_ + jg];
    const float bhn = b_hh[2 * H_ + jg];

    // weight bases pre-offset by (k-quarter, column)
    const ulonglong2* w1p = w1u + (kq * 16) * H_ + jg;
    const ulonglong2* w2p = w2u + (kq * 16) * H_ + jg;
    const ulonglong2* whp = whhu + (kq * 16) * (3 * H_) + jg;   // +H_ => z, +2H_ => n
    const ulonglong2* wip = wihu + (kq * 4) * (3 * H_) + jg;
    const ulonglong2* wop = woutu + (kq * 16) * H_ + jg;
    const float* vh = hbuf + 4 * (kq * 16);
    const float* vode = odebuf + 4 * (kq * 16);
    const float* va1 = a1buf + 4 * (kq * 16);
    const float* vx = xbuf + 4 * (kq * 4);

    // x/mask indices for the per-thread staging element
    const int xr = tid >> 6, xc = tid & 63;
    const size_t xbase = ((size_t)(row0 + xr) * T_) * D_ + xc;

    // preload t=0 x and mask, store before the first barrier
    xbuf[xr * XS + xc] = x[xbase];
    if (tid < ROWSC) smk[tid] = mask[(size_t)(row0 + tid) * T_];

    // stage-2 weight ring preloaded before the first barrier (in flight during it)
    ulonglong2 wbS2[8];
    PRELOAD8(wbS2, w1p, H_);

    cluster_sync_();

    for (int t = 0; t < T_; t++) {
        // ---- stage 2: a1 = tanh(h @ w1^T + b1) ----
        {
            ull acc[8] = {0ull, 0ull, 0ull, 0ull, 0ull, 0ull, 0ull, 0ull};
            gemm8p(acc, w1p, H_, vh, wbS2);
#pragma unroll
            for (int r = 0; r < 8; r++) PART4(kq, r, j0) = hadd2(acc[r]);
            __syncthreads();
            {
                float s0 = b1j + PART4(0, ro0, j0) + PART4(1, ro0, j0) + PART4(2, ro0, j0) + PART4(3, ro0, j0);
                float s1 = b1j + PART4(0, ro1, j0) + PART4(1, ro1, j0) + PART4(2, ro1, j0) + PART4(3, ro1, j0);
                float a0 = tanhf(s0), a1v = tanhf(s1);
                a1buf[ro0 * VS + jg] = a0;
                a1buf[ro1 * VS + jg] = a1v;
                sts_peer_f32(&a1buf[ro0 * VS + jg], peer, a0);
                sts_peer_f32(&a1buf[ro1 * VS + jg], peer, a1v);
            }
        }
        // a1-exchange barrier window: prefetch stage-3 weight ring
        cluster_arrive_();
        ulonglong2 wbS3[8];
        PRELOAD8(wbS3, w2p, H_);
        cluster_wait_();

        // ---- stage 3: f = a1 @ w2^T + b2 ; euler ; h_ode ----
        {
            ull acc[8] = {0ull, 0ull, 0ull, 0ull, 0ull, 0ull, 0ull, 0ull};
            gemm8p(acc, w2p, H_, va1, wbS3);
#pragma unroll
            for (int r = 0; r < 8; r++) PART4(kq, r, j0) = hadd2(acc[r]);
            __syncthreads();
            {
                const float dtv = sdt[t];
                float f0 = b2j + PART4(0, ro0, j0) + PART4(1, ro0, j0) + PART4(2, ro0, j0) + PART4(3, ro0, j0);
                float f1 = b2j + PART4(0, ro1, j0) + PART4(1, ro1, j0) + PART4(2, ro1, j0) + PART4(3, ro1, j0);
                float he0 = hc0 + dtv * f0;
                float he1 = hc1 + dtv * f1;
                ho0 = (se0 > 0.0f) ? he0 : hc0;
                ho1 = (se1 > 0.0f) ? he1 : hc1;
                odebuf[ro0 * VS + jg] = ho0;
                odebuf[ro1 * VS + jg] = ho1;
                sts_peer_f32(&odebuf[ro0 * VS + jg], peer, ho0);
                sts_peer_f32(&odebuf[ro1 * VS + jg], peer, ho1);
            }
        }
        // ode-exchange barrier window: x-gate GEMM + stage-4 weight prefetch
        cluster_arrive_();
        ulonglong2 wbr[3], wbz[3], wbn[3];
        {
            ull xR[8] = {0ull, 0ull, 0ull, 0ull, 0ull, 0ull, 0ull, 0ull};
            ull xZ[8] = {0ull, 0ull, 0ull, 0ull, 0ull, 0ull, 0ull, 0ull};
            ull xI[8] = {0ull, 0ull, 0ull, 0ull, 0ull, 0ull, 0ull, 0ull};
#pragma unroll
            for (int kk = 0; kk < 4; kk++) {
                ulonglong2 wr = wip[kk * (3 * H_)];
                ulonglong2 wz = wip[kk * (3 * H_) + H_];
                ulonglong2 wi = wip[kk * (3 * H_) + 2 * H_];
#pragma unroll
                for (int r = 0; r < 8; r++) {
                    ulonglong2 v = *reinterpret_cast<const ulonglong2*>(vx + r * XS + 4 * kk);
                    xR[r] = ffma2(wr.x, v.x, xR[r]); xR[r] = ffma2(wr.y, v.y, xR[r]);
                    xZ[r] = ffma2(wz.x, v.x, xZ[r]); xZ[r] = ffma2(wz.y, v.y, xZ[r]);
                    xI[r] = ffma2(wi.x, v.x, xI[r]); xI[r] = ffma2(wi.y, v.y, xI[r]);
                }
            }
            // stage-4 ring preload (in flight during the remaining barrier wait)
#pragma unroll
            for (int i = 0; i < 3; i++) {
                wbr[i] = whp[i * (3 * H_)];
                wbz[i] = whp[i * (3 * H_) + H_];
                wbn[i] = whp[i * (3 * H_) + 2 * H_];
            }
#pragma unroll
            for (int r = 0; r < 8; r++) {
                PART4(kq, 32 + r, j0) = hadd2(xR[r]);
                PART4(kq, 40 + r, j0) = hadd2(xZ[r]);
                PART4(kq, 24 + r, j0) = hadd2(xI[r]);
            }
        }
        cluster_wait_();

        // ---- stage 4: recurrent gates (r,z,n over h_ode), depth-3 pipelined weights ----
        {
            ull aR[8] = {0ull, 0ull, 0ull, 0ull, 0ull, 0ull, 0ull, 0ull};
            ull aZ[8] = {0ull, 0ull, 0ull, 0ull, 0ull, 0ull, 0ull, 0ull};
            ull aN[8] = {0ull, 0ull, 0ull, 0ull, 0ull, 0ull, 0ull, 0ull};
#pragma unroll
            for (int kk = 0; kk < 16; kk++) {
                int s = kk % 3;
                ulonglong2 wr = wbr[s];
                ulonglong2 wz = wbz[s];
                ulonglong2 wn = wbn[s];
                if (kk + 3 < 16) {
                    wbr[s] = whp[(kk + 3) * (3 * H_)];
                    wbz[s] = whp[(kk + 3) * (3 * H_) + H_];
                    wbn[s] = whp[(kk + 3) * (3 * H_) + 2 * H_];
                }
#pragma unroll
                for (int r = 0; r < 8; r++) {
                    ulonglong2 v = *reinterpret_cast<const ulonglong2*>(vode + r * VS + 4 * kk);
                    aR[r] = ffma2(wr.x, v.x, aR[r]); aR[r] = ffma2(wr.y, v.y, aR[r]);
                    aZ[r] = ffma2(wz.x, v.x, aZ[r]); aZ[r] = ffma2(wz.y, v.y, aZ[r]);
                    aN[r] = ffma2(wn.x, v.x, aN[r]); aN[r] = ffma2(wn.y, v.y, aN[r]);
                }
            }
#pragma unroll
            for (int r = 0; r < 8; r++) {
                PART4(kq, r, j0) = hadd2(aR[r]);
                PART4(kq, 8 + r, j0) = hadd2(aZ[r]);
                PART4(kq, 16 + r, j0) = hadd2(aN[r]);
            }
            __syncthreads();
            // owner reduces its 2 rows, applies gates, broadcasts h
            {
#pragma unroll
                for (int q2 = 0; q2 < 2; q2++) {
                    int r = (q2 == 0) ? ro0 : ro1;
                    float hoq = (q2 == 0) ? ho0 : ho1;
                    float fr = brz_r, fz = brz_z, fn = bhn, fi = bin_;
#pragma unroll
                    for (int q = 0; q < 4; q++) {
                        fr += PART4(q, r, j0) + PART4(q, 32 + r, j0);
                        fz += PART4(q, 8 + r, j0) + PART4(q, 40 + r, j0);
                        fn += PART4(q, 16 + r, j0);
                        fi += PART4(q, 24 + r, j0);
                    }
                    float rg = sigmoidf_(fr);
                    float zg = sigmoidf_(fz);
                    float ng = tanhf(fi + rg * fn);
                    float hrnn = (1.0f - zg) * ng + zg * hoq;
                    float m = smk[r];
                    float hn = (m > 0.5f) ? hrnn : hoq;
                    if (q2 == 0) {
                        hc0 = hn; hl0 = (m > 0.5f) ? hn : hl0; se0 = fmaxf(se0, m);
                    } else {
                        hc1 = hn; hl1 = (m > 0.5f) ? hn : hl1; se1 = fmaxf(se1, m);
                    }
                    hbuf[r * VS + jg] = hn;
                    sts_peer_f32(&hbuf[r * VS + jg], peer, hn);
                }
            }
        }
        // end-of-step barrier window: x_{t+1}/mask prefetch + stage-2 ring for next step
        cluster_arrive_();
        {
            float xn = 0.0f, mn = 0.0f;
            const bool more = (t + 1 < T_);
            if (more) {
                xn = x[xbase + (size_t)(t + 1) * D_];
                if (tid < ROWSC) mn = mask[(size_t)(row0 + tid) * T_ + (t + 1)];
                PRELOAD8(wbS2, w1p, H_);
            }
            cluster_wait_();
            if (more) {
                xbuf[xr * XS + xc] = xn;
                if (tid < ROWSC) smk[tid] = mn;
            }
        }
    }

    // ---- final projection: out = h_last @ w_out^T + b_out ----
    hbuf[ro0 * VS + jg] = hl0;
    hbuf[ro1 * VS + jg] = hl1;
    sts_peer_f32(&hbuf[ro0 * VS + jg], peer, hl0);
    sts_peer_f32(&hbuf[ro1 * VS + jg], peer, hl1);
    cluster_arrive_();
    ulonglong2 wbO[8];
    PRELOAD8(wbO, wop, H_);
    cluster_wait_();
    {
        ull acc[8] = {0ull, 0ull, 0ull, 0ull, 0ull, 0ull, 0ull, 0ull};
        gemm8p(acc, wop, H_, vh, wbO);
#pragma unroll
        for (int r = 0; r < 8; r++) PART4(kq, r, j0) = hadd2(acc[r]);
        __syncthreads();
        {
            const float bo = b_out[jg];
            float s0 = bo + PART4(0, ro0, j0) + PART4(1, ro0, j0) + PART4(2, ro0, j0) + PART4(3, ro0, j0);
            float s1 = bo + PART4(0, ro1, j0) + PART4(1, ro1, j0) + PART4(2, ro1, j0) + PART4(3, ro1, j0);
            out[(size_t)(row0 + ro0) * H_ + jg] = s0;
            out[(size_t)(row0 + ro1) * H_ + jg] = s1;
        }
    }
    cluster_sync_();
}

extern "C" void kernel_launch(void* const* d_in, const int* in_sizes, int n_in,
                              void* d_out, int out_size) {
    const float* x     = (const float*)d_in[0];
    const float* tps   = (const float*)d_in[1];
    const float* mask  = (const float*)d_in[2];
    const float* w_ih  = (const float*)d_in[3];
    const float* w_hh  = (const float*)d_in[4];
    const float* b_ih  = (const float*)d_in[5];
    const float* b_hh  = (const float*)d_in[6];
    const float* w1    = (const float*)d_in[7];
    const float* b1    = (const float*)d_in[8];
    const float* w2    = (const float*)d_in[9];
    const float* b2    = (const float*)d_in[10];
    const float* w_out = (const float*)d_in[11];
    const float* b_out = (const float*)d_in[12];
    float* out = (float*)d_out;

    static bool attr_set = false;
    if (!attr_set) {
        cudaFuncSetAttribute(gruode_kernel,
                             cudaFuncAttributeMaxDynamicSharedMemorySize, SMEM_BYTES);
        attr_set = true;
    }

    pack_all_kernel<<<(PK_TOTAL + 255) / 256, 256>>>(w1, w2, w_hh, w_ih, w_out, tps);
    gruode_kernel<<<NCTA, THREADS, SMEM_BYTES>>>(x, mask, b_ih, b_hh, b1, b2, b_out, out);
}

// round 16
// speedup vs baseline: 1.0924x; 1.0924x over previous
#include <cuda_runtime.h>
#include <cstdint>

#define T_ 256
#define D_ 64
#define H_ 256
#define B_ 512
#define ROWSC 8          // batch rows per cluster
#define JH 128           // output columns per CTA
#define NCTA 128
#define THREADS 512      // (kq:2) | (j0:7)

#define VS 260           // vector row stride (floats), 16B aligned
#define XS 68
#define NSLOT 48         // 0-7 r(A) | 8-15 z(A) | 16-23 n(A) | 24-31 i(x) | 32-39 r(x) | 40-47 z(x)

// dynamic smem layout (floats)
#define OFF_H    0
#define OFF_ODE  (OFF_H + ROWSC * VS)
#define OFF_A1   (OFF_ODE + ROWSC * VS)
#define OFF_X    (OFF_A1 + ROWSC * VS)
#define OFF_MK   (OFF_X + ROWSC * XS)
#define OFF_DT   (OFF_MK + 8)
#define OFF_PART (OFF_DT + T_)
#define SMEM_FLOATS (OFF_PART + 4 * NSLOT * JH)
#define SMEM_BYTES (SMEM_FLOATS * 4)

// packed: P[k4 * O + o] = float4{ W[o][4k4+0..3] }
__device__ float4 g_w1p[(H_ / 4) * H_];
__device__ float4 g_w2p[(H_ / 4) * H_];
__device__ float4 g_whhp[(H_ / 4) * (3 * H_)];
__device__ float4 g_wihp[(D_ / 4) * (3 * H_)];
__device__ float4 g_woutp[(H_ / 4) * H_];
__device__ float g_dt[T_];

#define N_W1 ((H_ / 4) * H_)
#define N_WHH ((H_ / 4) * (3 * H_))
#define N_WIH ((D_ / 4) * (3 * H_))
#define PK_TOTAL (3 * N_W1 + N_WHH + N_WIH)

__global__ void pack_all_kernel(const float* __restrict__ w1,
                                const float* __restrict__ w2,
                                const float* __restrict__ whh,
                                const float* __restrict__ wih,
                                const float* __restrict__ wout,
                                const float* __restrict__ tps) {
    int idx = blockIdx.x * blockDim.x + threadIdx.x;
    if (idx < T_) {
        g_dt[idx] = (idx == 0) ? (tps[0] - (tps[0] - 0.01f))
                               : (tps[idx] - tps[idx - 1]);
    }
    if (idx >= PK_TOTAL) return;
    const float* src; float4* dst; int O, K, local = idx;
    if (local < N_W1) { src = w1; dst = g_w1p; O = H_; K = H_; }
    else if ((local -= N_W1) < N_W1) { src = w2; dst = g_w2p; O = H_; K = H_; }
    else if ((local -= N_W1) < N_WHH) { src = whh; dst = g_whhp; O = 3 * H_; K = H_; }
    else if ((local -= N_WHH) < N_WIH) { src = wih; dst = g_wihp; O = 3 * H_; K = D_; }
    else { local -= N_WIH; src = wout; dst = g_woutp; O = H_; K = H_; }
    int k4 = local / O;
    int o = local % O;
    const float* s = src + (size_t)o * K + 4 * k4;
    dst[local] = make_float4(s[0], s[1], s[2], s[3]);
}

typedef unsigned long long ull;
__device__ __forceinline__ ull ffma2(ull a, ull b, ull c) {
    ull d; asm("fma.rn.f32x2 %0, %1, %2, %3;" : "=l"(d) : "l"(a), "l"(b), "l"(c)); return d;
}
__device__ __forceinline__ float hadd2(ull v) {
    float2 f; asm("mov.b64 {%0, %1}, %2;" : "=f"(f.x), "=f"(f.y) : "l"(v));
    return f.x + f.y;
}
__device__ __forceinline__ float sigmoidf_(float v) { return 1.0f / (1.0f + expf(-v)); }

__device__ __forceinline__ void sts_peer_f32(const void* laddr, uint32_t peer, float v) {
    uint32_t la = (uint32_t)__cvta_generic_to_shared(laddr), ra;
    asm("mapa.shared::cluster.u32 %0, %1, %2;" : "=r"(ra) : "r"(la), "r"(peer));
    asm volatile("st.shared::cluster.b32 [%0], %1;" :: "r"(ra), "r"(__float_as_uint(v)) : "memory");
}
__device__ __forceinline__ void cluster_sync_() {
    asm volatile("barrier.cluster.arrive.aligned;" ::: "memory");
    asm volatile("barrier.cluster.wait.aligned;" ::: "memory");
}
__device__ __forceinline__ void cluster_arrive_() {
    asm volatile("barrier.cluster.arrive.aligned;" ::: "memory");
}
__device__ __forceinline__ void cluster_wait_() {
    asm volatile("barrier.cluster.wait.aligned;" ::: "memory");
}

// 8-row GEMM over 16 quads, FULL weight preload (16 LDGs issued up front, then pure FMA).
// Ring lives only inside this scope — never across a barrier.
__device__ __forceinline__ void gemm8f(ull acc[8], const ulonglong2* __restrict__ wp, int wstep,
                                       const float* __restrict__ vbase) {
    ulonglong2 wb[16];
#pragma unroll
    for (int i = 0; i < 16; i++) wb[i] = wp[i * wstep];
#pragma unroll
    for (int kk = 0; kk < 16; kk++) {
        ulonglong2 w = wb[kk];
#pragma unroll
        for (int r = 0; r < 8; r++) {
            ulonglong2 v = *reinterpret_cast<const ulonglong2*>(vbase + r * VS + 4 * kk);
            acc[r] = ffma2(w.x, v.x, acc[r]);
            acc[r] = ffma2(w.y, v.y, acc[r]);
        }
    }
}

#define PART4(kq_, slot_, j_) sm[OFF_PART + ((kq_) * NSLOT + (slot_)) * JH + (j_)]

__global__ void __launch_bounds__(THREADS, 1) __cluster_dims__(2, 1, 1)
gruode_kernel(const float* __restrict__ x,
              const float* __restrict__ mask,
              const float* __restrict__ b_ih,
              const float* __restrict__ b_hh,
              const float* __restrict__ b1,
              const float* __restrict__ b2,
              const float* __restrict__ b_out,
              float* __restrict__ out) {
    extern __shared__ float sm[];
    float* hbuf = sm + OFF_H;
    float* odebuf = sm + OFF_ODE;
    float* a1buf = sm + OFF_A1;
    float* xbuf = sm + OFF_X;
    float* smk = sm + OFF_MK;
    float* sdt = sm + OFF_DT;

    const ulonglong2* w1u = reinterpret_cast<const ulonglong2*>(g_w1p);
    const ulonglong2* w2u = reinterpret_cast<const ulonglong2*>(g_w2p);
    const ulonglong2* whhu = reinterpret_cast<const ulonglong2*>(g_whhp);
    const ulonglong2* wihu = reinterpret_cast<const ulonglong2*>(g_wihp);
    const ulonglong2* woutu = reinterpret_cast<const ulonglong2*>(g_woutp);

    const int tid = threadIdx.x;
    const int j0 = tid & (JH - 1);
    const int kq = tid >> 7;           // 0..3 : k-quarter AND row-ownership (rows 2kq, 2kq+1)
    uint32_t rank;
    asm("mov.u32 %0, %%cluster_ctarank;" : "=r"(rank));
    const uint32_t peer = rank ^ 1u;
    const int jg = (int)rank * JH + j0;
    const int row0 = (blockIdx.x >> 1) * ROWSC;
    const int ro0 = 2 * kq, ro1 = 2 * kq + 1;

    for (int idx = tid; idx < ROWSC * VS; idx += THREADS) hbuf[idx] = 0.0f;
    for (int i = tid; i < T_; i += THREADS) sdt[i] = g_dt[i];

    float hc0 = 0.0f, hc1 = 0.0f, hl0 = 0.0f, hl1 = 0.0f;
    float se0 = 0.0f, se1 = 0.0f, ho0 = 0.0f, ho1 = 0.0f;

    const float b1j = b1[jg];
    const float b2j = b2[jg];
    const float brz_r = b_ih[jg] + b_hh[jg];
    const float brz_z = b_ih[H_ + jg] + b_hh[H_ + jg];
    const float bin_ = b_ih[2 * H_ + jg];
    const float bhn = b_hh[2 * H_ + jg];

    // weight bases pre-offset by (k-quarter, column)
    const ulonglong2* w1p = w1u + (kq * 16) * H_ + jg;
    const ulonglong2* w2p = w2u + (kq * 16) * H_ + jg;
    const ulonglong2* whp = whhu + (kq * 16) * (3 * H_) + jg;   // unified stream: index i*H_, i=3kk+g
    const ulonglong2* wip = wihu + (kq * 4) * (3 * H_) + jg;
    const ulonglong2* wop = woutu + (kq * 16) * H_ + jg;
    const float* vh = hbuf + 4 * (kq * 16);
    const float* vode = odebuf + 4 * (kq * 16);
    const float* va1 = a1buf + 4 * (kq * 16);
    const float* vx = xbuf + 4 * (kq * 4);

    // x/mask indices for the per-thread staging element
    const int xr = tid >> 6, xc = tid & 63;
    const size_t xbase = ((size_t)(row0 + xr) * T_) * D_ + xc;

    // preload t=0 x and mask, store before the first barrier
    xbuf[xr * XS + xc] = x[xbase];
    if (tid < ROWSC) smk[tid] = mask[(size_t)(row0 + tid) * T_];

    cluster_sync_();

    for (int t = 0; t < T_; t++) {
        // ---- stage 2: a1 = tanh(h @ w1^T + b1) ----
        {
            ull acc[8] = {0ull, 0ull, 0ull, 0ull, 0ull, 0ull, 0ull, 0ull};
            gemm8f(acc, w1p, H_, vh);
#pragma unroll
            for (int r = 0; r < 8; r++) PART4(kq, r, j0) = hadd2(acc[r]);
            __syncthreads();
            {
                float s0 = b1j + PART4(0, ro0, j0) + PART4(1, ro0, j0) + PART4(2, ro0, j0) + PART4(3, ro0, j0);
                float s1 = b1j + PART4(0, ro1, j0) + PART4(1, ro1, j0) + PART4(2, ro1, j0) + PART4(3, ro1, j0);
                float a0 = tanhf(s0), a1v = tanhf(s1);
                a1buf[ro0 * VS + jg] = a0;
                a1buf[ro1 * VS + jg] = a1v;
                sts_peer_f32(&a1buf[ro0 * VS + jg], peer, a0);
                sts_peer_f32(&a1buf[ro1 * VS + jg], peer, a1v);
            }
        }
        cluster_sync_();

        // ---- stage 3: f = a1 @ w2^T + b2 ; euler ; h_ode ----
        {
            ull acc[8] = {0ull, 0ull, 0ull, 0ull, 0ull, 0ull, 0ull, 0ull};
            gemm8f(acc, w2p, H_, va1);
#pragma unroll
            for (int r = 0; r < 8; r++) PART4(kq, r, j0) = hadd2(acc[r]);
            __syncthreads();
            {
                const float dtv = sdt[t];
                float f0 = b2j + PART4(0, ro0, j0) + PART4(1, ro0, j0) + PART4(2, ro0, j0) + PART4(3, ro0, j0);
                float f1 = b2j + PART4(0, ro1, j0) + PART4(1, ro1, j0) + PART4(2, ro1, j0) + PART4(3, ro1, j0);
                float he0 = hc0 + dtv * f0;
                float he1 = hc1 + dtv * f1;
                ho0 = (se0 > 0.0f) ? he0 : hc0;
                ho1 = (se1 > 0.0f) ? he1 : hc1;
                odebuf[ro0 * VS + jg] = ho0;
                odebuf[ro1 * VS + jg] = ho1;
                sts_peer_f32(&odebuf[ro0 * VS + jg], peer, ho0);
                sts_peer_f32(&odebuf[ro1 * VS + jg], peer, ho1);
            }
        }
        // overlap the ode-exchange barrier with the x-gate GEMM (depends only on xbuf)
        cluster_arrive_();
        {
            ull xR[8] = {0ull, 0ull, 0ull, 0ull, 0ull, 0ull, 0ull, 0ull};
            ull xZ[8] = {0ull, 0ull, 0ull, 0ull, 0ull, 0ull, 0ull, 0ull};
            ull xI[8] = {0ull, 0ull, 0ull, 0ull, 0ull, 0ull, 0ull, 0ull};
#pragma unroll
            for (int kk = 0; kk < 4; kk++) {
                ulonglong2 wr = wip[kk * (3 * H_)];
                ulonglong2 wz = wip[kk * (3 * H_) + H_];
                ulonglong2 wi = wip[kk * (3 * H_) + 2 * H_];
#pragma unroll
                for (int r = 0; r < 8; r++) {
                    ulonglong2 v = *reinterpret_cast<const ulonglong2*>(vx + r * XS + 4 * kk);
                    xR[r] = ffma2(wr.x, v.x, xR[r]); xR[r] = ffma2(wr.y, v.y, xR[r]);
                    xZ[r] = ffma2(wz.x, v.x, xZ[r]); xZ[r] = ffma2(wz.y, v.y, xZ[r]);
                    xI[r] = ffma2(wi.x, v.x, xI[r]); xI[r] = ffma2(wi.y, v.y, xI[r]);
                }
            }
#pragma unroll
            for (int r = 0; r < 8; r++) {
                PART4(kq, 32 + r, j0) = hadd2(xR[r]);
                PART4(kq, 40 + r, j0) = hadd2(xZ[r]);
                PART4(kq, 24 + r, j0) = hadd2(xI[r]);
            }
        }
        cluster_wait_();

        // ---- stage 4: recurrent gates (r,z,n over h_ode), unified depth-8 weight stream ----
        {
            ull aR[8] = {0ull, 0ull, 0ull, 0ull, 0ull, 0ull, 0ull, 0ull};
            ull aZ[8] = {0ull, 0ull, 0ull, 0ull, 0ull, 0ull, 0ull, 0ull};
            ull aN[8] = {0ull, 0ull, 0ull, 0ull, 0ull, 0ull, 0ull, 0ull};
            // unified stream: element i at whp[i*H_], i = 3*kk + gate (r=0,z=1,n=2)
            ulonglong2 wb[8];
#pragma unroll
            for (int i = 0; i < 8; i++) wb[i] = whp[i * H_];
#pragma unroll
            for (int kk = 0; kk < 16; kk++) {
                const int i0 = 3 * kk, i1 = 3 * kk + 1, i2 = 3 * kk + 2;
                ulonglong2 wr = wb[i0 & 7];
                if (i0 + 8 < 48) wb[i0 & 7] = whp[(i0 + 8) * H_];
                ulonglong2 wz = wb[i1 & 7];
                if (i1 + 8 < 48) wb[i1 & 7] = whp[(i1 + 8) * H_];
                ulonglong2 wn = wb[i2 & 7];
                if (i2 + 8 < 48) wb[i2 & 7] = whp[(i2 + 8) * H_];
#pragma unroll
                for (int r = 0; r < 8; r++) {
                    ulonglong2 v = *reinterpret_cast<const ulonglong2*>(vode + r * VS + 4 * kk);
                    aR[r] = ffma2(wr.x, v.x, aR[r]); aR[r] = ffma2(wr.y, v.y, aR[r]);
                    aZ[r] = ffma2(wz.x, v.x, aZ[r]); aZ[r] = ffma2(wz.y, v.y, aZ[r]);
                    aN[r] = ffma2(wn.x, v.x, aN[r]); aN[r] = ffma2(wn.y, v.y, aN[r]);
                }
            }
#pragma unroll
            for (int r = 0; r < 8; r++) {
                PART4(kq, r, j0) = hadd2(aR[r]);
                PART4(kq, 8 + r, j0) = hadd2(aZ[r]);
                PART4(kq, 16 + r, j0) = hadd2(aN[r]);
            }
            __syncthreads();
            // owner reduces its 2 rows, applies gates, broadcasts h
            {
#pragma unroll
                for (int q2 = 0; q2 < 2; q2++) {
                    int r = (q2 == 0) ? ro0 : ro1;
                    float hoq = (q2 == 0) ? ho0 : ho1;
                    float fr = brz_r, fz = brz_z, fn = bhn, fi = bin_;
#pragma unroll
                    for (int q = 0; q < 4; q++) {
                        fr += PART4(q, r, j0) + PART4(q, 32 + r, j0);
                        fz += PART4(q, 8 + r, j0) + PART4(q, 40 + r, j0);
                        fn += PART4(q, 16 + r, j0);
                        fi += PART4(q, 24 + r, j0);
                    }
                    float rg = sigmoidf_(fr);
                    float zg = sigmoidf_(fz);
                    float ng = tanhf(fi + rg * fn);
                    float hrnn = (1.0f - zg) * ng + zg * hoq;
                    float m = smk[r];
                    float hn = (m > 0.5f) ? hrnn : hoq;
                    if (q2 == 0) {
                        hc0 = hn; hl0 = (m > 0.5f) ? hn : hl0; se0 = fmaxf(se0, m);
                    } else {
                        hc1 = hn; hl1 = (m > 0.5f) ? hn : hl1; se1 = fmaxf(se1, m);
                    }
                    hbuf[r * VS + jg] = hn;
                    sts_peer_f32(&hbuf[r * VS + jg], peer, hn);
                }
            }
        }
        // overlap end-of-step barrier with x_{t+1}/mask prefetch
        cluster_arrive_();
        {
            float xn = 0.0f, mn = 0.0f;
            const bool more = (t + 1 < T_);
            if (more) {
                xn = x[xbase + (size_t)(t + 1) * D_];
                if (tid < ROWSC) mn = mask[(size_t)(row0 + tid) * T_ + (t + 1)];
            }
            cluster_wait_();
            if (more) {
                xbuf[xr * XS + xc] = xn;
                if (tid < ROWSC) smk[tid] = mn;
            }
        }
    }

    // ---- final projection: out = h_last @ w_out^T + b_out ----
    hbuf[ro0 * VS + jg] = hl0;
    hbuf[ro1 * VS + jg] = hl1;
    sts_peer_f32(&hbuf[ro0 * VS + jg], peer, hl0);
    sts_peer_f32(&hbuf[ro1 * VS + jg], peer, hl1);
    cluster_sync_();
    {
        ull acc[8] = {0ull, 0ull, 0ull, 0ull, 0ull, 0ull, 0ull, 0ull};
        gemm8f(acc, wop, H_, vh);
#pragma unroll
        for (int r = 0; r < 8; r++) PART4(kq, r, j0) = hadd2(acc[r]);
        __syncthreads();
        {
            const float bo = b_out[jg];
            float s0 = bo + PART4(0, ro0, j0) + PART4(1, ro0, j0) + PART4(2, ro0, j0) + PART4(3, ro0, j0);
            float s1 = bo + PART4(0, ro1, j0) + PART4(1, ro1, j0) + PART4(2, ro1, j0) + PART4(3, ro1, j0);
            out[(size_t)(row0 + ro0) * H_ + jg] = s0;
            out[(size_t)(row0 + ro1) * H_ + jg] = s1;
        }
    }
    cluster_sync_();
}

extern "C" void kernel_launch(void* const* d_in, const int* in_sizes, int n_in,
                              void* d_out, int out_size) {
    const float* x     = (const float*)d_in[0];
    const float* tps   = (const float*)d_in[1];
    const float* mask  = (const float*)d_in[2];
    const float* w_ih  = (const float*)d_in[3];
    const float* w_hh  = (const float*)d_in[4];
    const float* b_ih  = (const float*)d_in[5];
    const float* b_hh  = (const float*)d_in[6];
    const float* w1    = (const float*)d_in[7];
    const float* b1    = (const float*)d_in[8];
    const float* w2    = (const float*)d_in[9];
    const float* b2    = (const float*)d_in[10];
    const float* w_out = (const float*)d_in[11];
    const float* b_out = (const float*)d_in[12];
    float* out = (float*)d_out;

    static bool attr_set = false;
    if (!attr_set) {
        cudaFuncSetAttribute(gruode_kernel,
                             cudaFuncAttributeMaxDynamicSharedMemorySize, SMEM_BYTES);
        attr_set = true;
    }

    pack_all_kernel<<<(PK_TOTAL + 255) / 256, 256>>>(w1, w2, w_hh, w_ih, w_out, tps);
    gruode_kernel<<<NCTA, THREADS, SMEM_BYTES>>>(x, mask, b_ih, b_hh, b1, b2, b_out, out);
}